// round 1
// baseline (speedup 1.0000x reference)
#include <cuda_runtime.h>
#include <math.h>
#include <cstdint>

#define L_ 512
#define B_ 64
#define E_ 256
#define H_ 256
#define T_ 12

// ---------------- scratch (static device allocations; no cudaMalloc) ----------------
__device__ float g_gx[(size_t)2*L_*B_*1024];   // input gates (incl bias): [2][L][B][4H]  (256 MB)
__device__ float g_h [(size_t)2*L_*B_*H_];     // hidden states: [2][L][B][H]             (64 MB)
__device__ float g_emit[(size_t)L_*B_*T_];     // emissions: [L][B][T]
__device__ float g_nll[B_];
__device__ int   g_flag[2*L_];                 // per-(dir,step) producer arrival counts

// ---------------- flag reset (graph replays reuse the flags) ----------------
__global__ void k_reset() {
    int i = threadIdx.x;
    if (i < 2*L_) g_flag[i] = 0;
}

// ---------------- input-gate GEMM: g_gx[d][l][b][j] = W_ih[d][j] . emb[sent[b][l]] + b[d][j]
// grid (L, 8); 256 threads; CTA tile = 64 batch rows (one l) x 256 gate cols; K=256
__global__ __launch_bounds__(256) void k_ingate(
    const int* __restrict__ sent, const float* __restrict__ emb,
    const float* __restrict__ Wf, const float* __restrict__ bfv,
    const float* __restrict__ Wb, const float* __restrict__ bbv)
{
    extern __shared__ float Xs[];       // [64][256] embedding rows
    __shared__ int tok[B_];
    int l   = blockIdx.x;
    int tid = threadIdx.x;
    if (tid < B_) tok[tid] = sent[tid*L_ + l];   // sentences is [B][L]
    __syncthreads();
    float4* Xs4 = (float4*)Xs;
    #pragma unroll
    for (int i = 0; i < 16; i++) {
        int e = i*256 + tid;
        int r = e >> 6, kq = e & 63;
        Xs4[e] = ((const float4*)emb)[(size_t)tok[r]*64 + kq];
    }
    __syncthreads();

    int j   = blockIdx.y*256 + tid;     // global col 0..2047 (both directions)
    int dir = j >> 10, jj = j & 1023;
    const float*  W  = dir ? Wb : Wf;
    const float4* W4 = (const float4*)(W + (size_t)jj*256);

    float acc[64];
    #pragma unroll
    for (int r = 0; r < 64; r++) acc[r] = 0.f;

    for (int k4 = 0; k4 < 64; k4++) {
        float4 w = W4[k4];
        #pragma unroll
        for (int r = 0; r < 64; r++) {
            float4 x = Xs4[r*64 + k4];
            acc[r] += w.x*x.x + w.y*x.y + w.z*x.z + w.w*x.w;
        }
    }
    float bias = (dir ? bbv : bfv)[jj];
    float* outp = g_gx + (((size_t)dir*L_ + l)*B_)*1024 + jj;
    #pragma unroll
    for (int r = 0; r < 64; r++) outp[(size_t)r*1024] = acc[r] + bias;
}

// ---------------- persistent bidirectional LSTM recurrence ----------------
// 128 CTAs: cid>>6 = direction, cid&63 = 4-hidden-unit slice. 256 threads = 64 batch x 4 hid.
// Per step: load full h[t_prev] into smem, gate-GEMM from smem W_hh slice, write h slice,
// fence, bump per-step flag; consumers spin on flag==64.
__global__ __launch_bounds__(256) void k_lstm(const float* __restrict__ Whf,
                                              const float* __restrict__ Whb)
{
    extern __shared__ float sm[];
    float* Hs = sm;              // [64][260] padded (conflict-free)
    float* Ws = sm + 64*260;     // [16][260] : 4 gates x 4 local hid x 256
    int cid = blockIdx.x;
    int d   = cid >> 6;
    int hb  = (cid & 63) * 4;
    int tid = threadIdx.x;
    int b   = tid >> 2, jl = tid & 3;
    const float* W = d ? Whb : Whf;

    for (int i = 0; i < 16; i++) {
        int e = i*256 + tid;                 // 16 rows x 256
        int rl = e >> 8, k = e & 255;
        int g = rl >> 2, j2 = rl & 3;        // rl = g*4 + j2
        Ws[rl*260 + k] = W[((size_t)(g*H_ + hb + j2))*H_ + k];
    }

    float c  = 0.f;
    int hid  = hb + jl;
    volatile int* flg = g_flag;

    for (int s = 0; s < L_; s++) {
        int t = d ? (L_-1-s) : s;
        // input gates (independent of h) — issue before the wait to hide DRAM latency
        const float* gx = g_gx + (((size_t)d*L_ + t)*B_ + b)*1024 + hid;
        float a0 = gx[0], a1 = gx[256], a2 = gx[512], a3 = gx[768];

        if (s == 0) {
            #pragma unroll
            for (int i = 0; i < 16; i++) {
                int e = i*256 + tid; int r = e >> 6, kq = e & 63;
                ((float4*)(Hs + r*260))[kq] = make_float4(0.f,0.f,0.f,0.f);
            }
        } else {
            int tprev = d ? (t+1) : (t-1);
            if (tid == 0) {
                while (flg[d*L_ + tprev] < 64) { }
                __threadfence();
            }
            __syncthreads();
            const float4* src = (const float4*)(g_h + (((size_t)d*L_ + tprev)*B_)*H_);
            #pragma unroll
            for (int i = 0; i < 16; i++) {
                int e = i*256 + tid; int r = e >> 6, kq = e & 63;
                ((float4*)(Hs + r*260))[kq] = src[e];
            }
        }
        __syncthreads();

        const float4* hrow = (const float4*)(Hs + b*260);
        const float4* w0p  = (const float4*)(Ws + ( 0+jl)*260);
        const float4* w1p  = (const float4*)(Ws + ( 4+jl)*260);
        const float4* w2p  = (const float4*)(Ws + ( 8+jl)*260);
        const float4* w3p  = (const float4*)(Ws + (12+jl)*260);
        #pragma unroll 8
        for (int k4 = 0; k4 < 64; k4++) {
            float4 x  = hrow[k4];
            float4 w0 = w0p[k4], w1 = w1p[k4], w2 = w2p[k4], w3 = w3p[k4];
            a0 += w0.x*x.x + w0.y*x.y + w0.z*x.z + w0.w*x.w;
            a1 += w1.x*x.x + w1.y*x.y + w1.z*x.z + w1.w*x.w;
            a2 += w2.x*x.x + w2.y*x.y + w2.z*x.z + w2.w*x.w;
            a3 += w3.x*x.x + w3.y*x.y + w3.z*x.z + w3.w*x.w;
        }
        float ig = 1.f/(1.f + __expf(-a0));
        float fg = 1.f/(1.f + __expf(-a1));
        float gg = tanhf(a2);
        float og = 1.f/(1.f + __expf(-a3));
        c = fg*c + ig*gg;
        float h = og * tanhf(c);
        g_h[(((size_t)d*L_ + t)*B_ + b)*H_ + hid] = h;
        __threadfence();
        __syncthreads();
        if (tid == 0) atomicAdd(&g_flag[d*L_ + t], 1);
    }
}

// ---------------- emission: emit[l][b][t] = [h_f|h_b] . W_emit[t] + b_emit[t] ----------------
__global__ __launch_bounds__(768) void k_emit(const float* __restrict__ Wem,
                                              const float* __restrict__ bem)
{
    extern __shared__ float smc[];
    float* Hcat = smc;            // [64][520] padded
    float* Wsm  = smc + 64*520;   // [12][516] padded
    int l   = blockIdx.x;
    int tid = threadIdx.x;
    const float4* hf  = (const float4*)(g_h + ((size_t)0*L_ + l)*B_*H_);
    const float4* hbk = (const float4*)(g_h + ((size_t)1*L_ + l)*B_*H_);
    for (int e = tid; e < 4096; e += 768) {
        int r = e >> 6, kq = e & 63;
        ((float4*)(Hcat + r*520))[kq]       = hf[e];
        ((float4*)(Hcat + r*520 + 256))[kq] = hbk[e];
    }
    for (int e = tid; e < 12*512; e += 768)
        Wsm[(e >> 9)*516 + (e & 511)] = Wem[e];
    __syncthreads();

    int b = tid / 12, tg = tid - b*12;      // 768 = 64*12 exact
    float acc = bem[tg];
    const float4* hrow = (const float4*)(Hcat + b*520);
    const float4* wrow = (const float4*)(Wsm + tg*516);
    #pragma unroll 8
    for (int k4 = 0; k4 < 128; k4++) {
        float4 x = hrow[k4]; float4 w = wrow[k4];
        acc += w.x*x.x + w.y*x.y + w.z*x.z + w.w*x.w;
    }
    g_emit[((size_t)l*B_ + b)*T_ + tg] = acc;
}

// ---------------- CRF NLL per batch element: one warp per b ----------------
__global__ void k_crf(const int* __restrict__ tags, const float* __restrict__ trans)
{
    int b = blockIdx.x;
    int lane = threadIdx.x;
    __shared__ float tr[T_*T_];
    for (int i = lane; i < T_*T_; i += 32) tr[i] = trans[i];
    __syncwarp();
    const unsigned FULL = 0xffffffffu;
    int mylane = (lane < T_) ? lane : 0;
    float alpha = (lane < T_) ? g_emit[(size_t)b*T_ + lane] : 0.f;
    for (int l = 1; l < L_; l++) {
        float v[T_];
        float m = -1e30f;
        #pragma unroll
        for (int t2 = 0; t2 < T_; t2++) {
            float at = __shfl_sync(FULL, alpha, t2);
            float vv = at + tr[t2*T_ + mylane];
            v[t2] = vv;
            m = fmaxf(m, vv);
        }
        float ssum = 0.f;
        #pragma unroll
        for (int t2 = 0; t2 < T_; t2++) ssum += __expf(v[t2] - m);
        float e = (lane < T_) ? g_emit[((size_t)l*B_ + b)*T_ + lane] : 0.f;
        alpha = m + __logf(ssum) + e;
    }
    float am = (lane < T_) ? alpha : -1e30f;
    float mm = am;
    for (int o = 16; o; o >>= 1) mm = fmaxf(mm, __shfl_xor_sync(FULL, mm, o));
    float es = (lane < T_) ? __expf(alpha - mm) : 0.f;
    for (int o = 16; o; o >>= 1) es += __shfl_xor_sync(FULL, es, o);
    float logZ = mm + __logf(es);

    float eg = 0.f, tg2 = 0.f;
    for (int l = lane; l < L_; l += 32) {
        int tv = tags[b*L_ + l];
        eg += g_emit[((size_t)l*B_ + b)*T_ + tv];
    }
    for (int l = lane; l < L_-1; l += 32) {
        int t0v = tags[b*L_ + l], t1v = tags[b*L_ + l + 1];
        tg2 += tr[t0v*T_ + t1v];
    }
    for (int o = 16; o; o >>= 1) {
        eg  += __shfl_xor_sync(FULL, eg,  o);
        tg2 += __shfl_xor_sync(FULL, tg2, o);
    }
    if (lane == 0) g_nll[b] = logZ - eg - tg2;
}

__global__ void k_mean(float* out)
{
    if (threadIdx.x == 0) {
        float s = 0.f;
        for (int i = 0; i < B_; i++) s += g_nll[i];
        out[0] = s / (float)B_;
    }
}

// ---------------- launch ----------------
extern "C" void kernel_launch(void* const* d_in, const int* in_sizes, int n_in,
                              void* d_out, int out_size)
{
    const int*   sent  = (const int*)  d_in[0];
    const int*   tags  = (const int*)  d_in[1];
    const float* emb   = (const float*)d_in[2];
    const float* Wihf  = (const float*)d_in[3];
    const float* Whhf  = (const float*)d_in[4];
    const float* bf    = (const float*)d_in[5];
    const float* Wihb  = (const float*)d_in[6];
    const float* Whhb  = (const float*)d_in[7];
    const float* bb    = (const float*)d_in[8];
    const float* Wem   = (const float*)d_in[9];
    const float* bem   = (const float*)d_in[10];
    const float* trans = (const float*)d_in[11];
    float* out = (float*)d_out;

    cudaFuncSetAttribute(k_ingate, cudaFuncAttributeMaxDynamicSharedMemorySize, 64*256*4);
    cudaFuncSetAttribute(k_lstm,   cudaFuncAttributeMaxDynamicSharedMemorySize, (64*260 + 16*260)*4);
    cudaFuncSetAttribute(k_emit,   cudaFuncAttributeMaxDynamicSharedMemorySize, (64*520 + 12*516)*4);

    k_reset<<<1, 1024>>>();
    dim3 gA(L_, 8);
    k_ingate<<<gA, 256, 64*256*4>>>(sent, emb, Wihf, bf, Wihb, bb);
    k_lstm<<<128, 256, (64*260 + 16*260)*4>>>(Whhf, Whhb);
    k_emit<<<L_, 768, (64*520 + 12*516)*4>>>(Wem, bem);
    k_crf<<<B_, 32>>>(tags, trans);
    k_mean<<<1, 32>>>(out);
}

// round 2
// speedup vs baseline: 1.0500x; 1.0500x over previous
#include <cuda_runtime.h>
#include <math.h>
#include <cstdint>

#define L_ 512
#define B_ 64
#define E_ 256
#define H_ 256
#define T_ 12

typedef unsigned long long u64;

__device__ __forceinline__ u64 fma2(u64 a, u64 b, u64 c) {
    u64 d;
    asm("fma.rn.f32x2 %0, %1, %2, %3;" : "=l"(d) : "l"(a), "l"(b), "l"(c));
    return d;
}
__device__ __forceinline__ float2 unpack2(u64 v) {
    float2 r;
    asm("mov.b64 {%0, %1}, %2;" : "=f"(r.x), "=f"(r.y) : "l"(v));
    return r;
}

// ---------------- scratch (static device allocations; no cudaMalloc) ----------------
__device__ float g_gx[(size_t)2*L_*B_*1024];   // input gates (incl bias): [2][L][B][4H]
__device__ float g_h [(size_t)2*L_*B_*H_];     // hidden states: [2][L][B][H]
__device__ float g_emit[(size_t)L_*B_*T_];     // emissions: [L][B][T]
__device__ float g_nll[B_];
__device__ int   g_flag[2*L_];                 // per-(dir,step) producer arrival counts

__global__ void k_reset() {
    int i = threadIdx.x;
    if (i < 2*L_) g_flag[i] = 0;
}

// ---------------- input-gate GEMM (f32x2 packed) ----------------
// grid (L, 8); 256 threads; CTA tile = 64 batch rows (one l) x 256 gate cols; K=256
__global__ __launch_bounds__(256, 1) void k_ingate(
    const int* __restrict__ sent, const float* __restrict__ emb,
    const float* __restrict__ Wf, const float* __restrict__ bfv,
    const float* __restrict__ Wb, const float* __restrict__ bbv)
{
    extern __shared__ float Xs[];       // [64][256] embedding rows
    __shared__ int tok[B_];
    int l   = blockIdx.x;
    int tid = threadIdx.x;
    if (tid < B_) tok[tid] = sent[tid*L_ + l];
    __syncthreads();
    float4* Xs4 = (float4*)Xs;
    #pragma unroll
    for (int i = 0; i < 16; i++) {
        int e = i*256 + tid;
        int r = e >> 6, kq = e & 63;
        Xs4[e] = ((const float4*)emb)[(size_t)tok[r]*64 + kq];
    }
    __syncthreads();

    int j   = blockIdx.y*256 + tid;
    int dir = j >> 10, jj = j & 1023;
    const float* W = dir ? Wb : Wf;
    const ulonglong2* W2 = (const ulonglong2*)(W + (size_t)jj*256);
    const ulonglong2* X2 = (const ulonglong2*)Xs;

    u64 acc2[64];
    #pragma unroll
    for (int r = 0; r < 64; r++) acc2[r] = 0ull;   // bits of (0.f, 0.f)

    #pragma unroll 1
    for (int k4 = 0; k4 < 64; k4++) {
        ulonglong2 w = W2[k4];
        #pragma unroll
        for (int r = 0; r < 64; r++) {
            ulonglong2 x = X2[r*64 + k4];
            acc2[r] = fma2(w.x, x.x, acc2[r]);
            acc2[r] = fma2(w.y, x.y, acc2[r]);
        }
    }
    float bias = (dir ? bbv : bfv)[jj];
    float* outp = g_gx + (((size_t)dir*L_ + l)*B_)*1024 + jj;
    #pragma unroll
    for (int r = 0; r < 64; r++) {
        float2 p = unpack2(acc2[r]);
        outp[(size_t)r*1024] = p.x + p.y + bias;
    }
}

// ---------------- persistent bidirectional LSTM recurrence ----------------
// 128 CTAs: cid>>6 = direction, cid&63 = 4-hidden-unit slice. 256 threads = 64 batch x 4 hid.
__global__ __launch_bounds__(256) void k_lstm(const float* __restrict__ Whf,
                                              const float* __restrict__ Whb)
{
    extern __shared__ float sm[];
    float* Hs = sm;              // [64][260] padded
    float* Ws = sm + 64*260;     // [16][260] : 4 gates x 4 local hid x 256
    int cid = blockIdx.x;
    int d   = cid >> 6;
    int hb  = (cid & 63) * 4;
    int tid = threadIdx.x;
    int b   = tid >> 2, jl = tid & 3;
    const float* W = d ? Whb : Whf;

    for (int i = 0; i < 16; i++) {
        int e = i*256 + tid;
        int rl = e >> 8, k = e & 255;
        int g = rl >> 2, j2 = rl & 3;
        Ws[rl*260 + k] = W[((size_t)(g*H_ + hb + j2))*H_ + k];
    }

    float c  = 0.f;
    int hid  = hb + jl;

    for (int s = 0; s < L_; s++) {
        int t = d ? (L_-1-s) : s;
        // input gates (independent of h) — issue before the wait to hide DRAM latency
        const float* gx = g_gx + (((size_t)d*L_ + t)*B_ + b)*1024 + hid;
        float a0 = gx[0], a1 = gx[256], a2 = gx[512], a3 = gx[768];

        if (s == 0) {
            #pragma unroll
            for (int i = 0; i < 16; i++) {
                int e = i*256 + tid; int r = e >> 6, kq = e & 63;
                ((float4*)(Hs + r*260))[kq] = make_float4(0.f,0.f,0.f,0.f);
            }
        } else {
            int tprev = d ? (t+1) : (t-1);
            if (tid == 0) {
                const int* fp = g_flag + d*L_ + tprev;
                int v;
                do {
                    asm volatile("ld.acquire.gpu.b32 %0, [%1];" : "=r"(v) : "l"(fp) : "memory");
                } while (v < 64);
            }
            __syncthreads();
            const float4* src = (const float4*)(g_h + (((size_t)d*L_ + tprev)*B_)*H_);
            #pragma unroll
            for (int i = 0; i < 16; i++) {
                int e = i*256 + tid; int r = e >> 6, kq = e & 63;
                ((float4*)(Hs + r*260))[kq] = src[e];
            }
        }
        __syncthreads();

        const ulonglong2* hrow = (const ulonglong2*)(Hs + b*260);
        const ulonglong2* w0p  = (const ulonglong2*)(Ws + ( 0+jl)*260);
        const ulonglong2* w1p  = (const ulonglong2*)(Ws + ( 4+jl)*260);
        const ulonglong2* w2p  = (const ulonglong2*)(Ws + ( 8+jl)*260);
        const ulonglong2* w3p  = (const ulonglong2*)(Ws + (12+jl)*260);
        u64 A0 = 0ull, A1 = 0ull, A2 = 0ull, A3 = 0ull;
        #pragma unroll 8
        for (int k4 = 0; k4 < 64; k4++) {
            ulonglong2 x  = hrow[k4];
            ulonglong2 w0 = w0p[k4], w1 = w1p[k4], w2 = w2p[k4], w3 = w3p[k4];
            A0 = fma2(w0.x, x.x, A0); A0 = fma2(w0.y, x.y, A0);
            A1 = fma2(w1.x, x.x, A1); A1 = fma2(w1.y, x.y, A1);
            A2 = fma2(w2.x, x.x, A2); A2 = fma2(w2.y, x.y, A2);
            A3 = fma2(w3.x, x.x, A3); A3 = fma2(w3.y, x.y, A3);
        }
        float2 p0 = unpack2(A0), p1 = unpack2(A1), p2 = unpack2(A2), p3 = unpack2(A3);
        a0 += p0.x + p0.y; a1 += p1.x + p1.y; a2 += p2.x + p2.y; a3 += p3.x + p3.y;

        float ig = 1.f/(1.f + __expf(-a0));
        float fg = 1.f/(1.f + __expf(-a1));
        float gg = tanhf(a2);
        float og = 1.f/(1.f + __expf(-a3));
        c = fg*c + ig*gg;
        float h = og * tanhf(c);
        g_h[(((size_t)d*L_ + t)*B_ + b)*H_ + hid] = h;
        __syncthreads();
        if (tid == 0) {
            __threadfence();                    // gpu-scope release (fence elevation after barrier)
            atomicAdd(&g_flag[d*L_ + t], 1);
        }
    }
}

// ---------------- emission GEMM ----------------
__global__ __launch_bounds__(768) void k_emit(const float* __restrict__ Wem,
                                              const float* __restrict__ bem)
{
    extern __shared__ float smc[];
    float* Hcat = smc;            // [64][520] padded
    float* Wsm  = smc + 64*520;   // [12][516] padded
    int l   = blockIdx.x;
    int tid = threadIdx.x;
    const float4* hf  = (const float4*)(g_h + ((size_t)0*L_ + l)*B_*H_);
    const float4* hbk = (const float4*)(g_h + ((size_t)1*L_ + l)*B_*H_);
    for (int e = tid; e < 4096; e += 768) {
        int r = e >> 6, kq = e & 63;
        ((float4*)(Hcat + r*520))[kq]       = hf[e];
        ((float4*)(Hcat + r*520 + 256))[kq] = hbk[e];
    }
    for (int e = tid; e < 12*512; e += 768)
        Wsm[(e >> 9)*516 + (e & 511)] = Wem[e];
    __syncthreads();

    int b = tid / 12, tg = tid - b*12;
    float acc = bem[tg];
    const float4* hrow = (const float4*)(Hcat + b*520);
    const float4* wrow = (const float4*)(Wsm + tg*516);
    #pragma unroll 8
    for (int k4 = 0; k4 < 128; k4++) {
        float4 x = hrow[k4]; float4 w = wrow[k4];
        acc += w.x*x.x + w.y*x.y + w.z*x.z + w.w*x.w;
    }
    g_emit[((size_t)l*B_ + b)*T_ + tg] = acc;
}

// ---------------- CRF NLL per batch element: one warp per b ----------------
__global__ void k_crf(const int* __restrict__ tags, const float* __restrict__ trans)
{
    int b = blockIdx.x;
    int lane = threadIdx.x;
    __shared__ float tr[T_*T_];
    for (int i = lane; i < T_*T_; i += 32) tr[i] = trans[i];
    __syncwarp();
    const unsigned FULL = 0xffffffffu;
    int mylane = (lane < T_) ? lane : 0;
    float alpha = (lane < T_) ? g_emit[(size_t)b*T_ + lane] : 0.f;
    for (int l = 1; l < L_; l++) {
        float v[T_];
        float m = -1e30f;
        #pragma unroll
        for (int t2 = 0; t2 < T_; t2++) {
            float at = __shfl_sync(FULL, alpha, t2);
            float vv = at + tr[t2*T_ + mylane];
            v[t2] = vv;
            m = fmaxf(m, vv);
        }
        float ssum = 0.f;
        #pragma unroll
        for (int t2 = 0; t2 < T_; t2++) ssum += __expf(v[t2] - m);
        float e = (lane < T_) ? g_emit[((size_t)l*B_ + b)*T_ + lane] : 0.f;
        alpha = m + __logf(ssum) + e;
    }
    float am = (lane < T_) ? alpha : -1e30f;
    float mm = am;
    for (int o = 16; o; o >>= 1) mm = fmaxf(mm, __shfl_xor_sync(FULL, mm, o));
    float es = (lane < T_) ? __expf(alpha - mm) : 0.f;
    for (int o = 16; o; o >>= 1) es += __shfl_xor_sync(FULL, es, o);
    float logZ = mm + __logf(es);

    float eg = 0.f, tg2 = 0.f;
    for (int l = lane; l < L_; l += 32) {
        int tv = tags[b*L_ + l];
        eg += g_emit[((size_t)l*B_ + b)*T_ + tv];
    }
    for (int l = lane; l < L_-1; l += 32) {
        int t0v = tags[b*L_ + l], t1v = tags[b*L_ + l + 1];
        tg2 += tr[t0v*T_ + t1v];
    }
    for (int o = 16; o; o >>= 1) {
        eg  += __shfl_xor_sync(FULL, eg,  o);
        tg2 += __shfl_xor_sync(FULL, tg2, o);
    }
    if (lane == 0) g_nll[b] = logZ - eg - tg2;
}

__global__ void k_mean(float* out)
{
    if (threadIdx.x == 0) {
        float s = 0.f;
        for (int i = 0; i < B_; i++) s += g_nll[i];
        out[0] = s / (float)B_;
    }
}

// ---------------- launch ----------------
extern "C" void kernel_launch(void* const* d_in, const int* in_sizes, int n_in,
                              void* d_out, int out_size)
{
    const int*   sent  = (const int*)  d_in[0];
    const int*   tags  = (const int*)  d_in[1];
    const float* emb   = (const float*)d_in[2];
    const float* Wihf  = (const float*)d_in[3];
    const float* Whhf  = (const float*)d_in[4];
    const float* bf    = (const float*)d_in[5];
    const float* Wihb  = (const float*)d_in[6];
    const float* Whhb  = (const float*)d_in[7];
    const float* bb    = (const float*)d_in[8];
    const float* Wem   = (const float*)d_in[9];
    const float* bem   = (const float*)d_in[10];
    const float* trans = (const float*)d_in[11];
    float* out = (float*)d_out;

    cudaFuncSetAttribute(k_ingate, cudaFuncAttributeMaxDynamicSharedMemorySize, 64*256*4);
    cudaFuncSetAttribute(k_lstm,   cudaFuncAttributeMaxDynamicSharedMemorySize, (64*260 + 16*260)*4);
    cudaFuncSetAttribute(k_emit,   cudaFuncAttributeMaxDynamicSharedMemorySize, (64*520 + 12*516)*4);

    k_reset<<<1, 1024>>>();
    dim3 gA(L_, 8);
    k_ingate<<<gA, 256, 64*256*4>>>(sent, emb, Wihf, bf, Wihb, bb);
    k_lstm<<<128, 256, (64*260 + 16*260)*4>>>(Whhf, Whhb);
    k_emit<<<L_, 768, (64*520 + 12*516)*4>>>(Wem, bem);
    k_crf<<<B_, 32>>>(tags, trans);
    k_mean<<<1, 32>>>(out);
}

// round 3
// speedup vs baseline: 1.2725x; 1.2119x over previous
#include <cuda_runtime.h>
#include <math.h>
#include <cstdint>

#define L_ 512
#define B_ 64
#define E_ 256
#define H_ 256
#define T_ 12

typedef unsigned long long u64;

__device__ __forceinline__ u64 fma2(u64 a, u64 b, u64 c) {
    u64 d;
    asm("fma.rn.f32x2 %0, %1, %2, %3;" : "=l"(d) : "l"(a), "l"(b), "l"(c));
    return d;
}
__device__ __forceinline__ float2 unpack2(u64 v) {
    float2 r;
    asm("mov.b64 {%0, %1}, %2;" : "=f"(r.x), "=f"(r.y) : "l"(v));
    return r;
}
__device__ __forceinline__ void st_release(int* p, int v) {
    asm volatile("st.release.gpu.global.b32 [%0], %1;" :: "l"(p), "r"(v) : "memory");
}
__device__ __forceinline__ int ld_acquire(const int* p) {
    int v;
    asm volatile("ld.acquire.gpu.global.b32 %0, [%1];" : "=r"(v) : "l"(p) : "memory");
    return v;
}
__device__ __forceinline__ float fsig(float x) {
    return __fdividef(1.f, 1.f + __expf(-x));
}
__device__ __forceinline__ float ftanh(float x) {
    float e2 = __expf(2.f * x);
    return 1.f - __fdividef(2.f, e2 + 1.f);
}

// ---------------- scratch (static device allocations; no cudaMalloc) ----------------
__device__ float g_gx[(size_t)2*L_*B_*1024];   // input gates (incl bias): [2][L][B][4H]
__device__ float g_h [(size_t)2*L_*B_*H_];     // hidden states: [2][L][B][H]
__device__ float g_emit[(size_t)L_*B_*T_];     // emissions: [L][B][T]
__device__ float g_nll[B_];
__device__ int   g_cnt[2*64];                  // per-(dir,producer) monotonic step counter

__global__ void k_reset() {
    int i = threadIdx.x;
    if (i < 2*64) g_cnt[i] = 0;
}

// ---------------- input-gate GEMM (f32x2 packed) ----------------
__global__ __launch_bounds__(256, 1) void k_ingate(
    const int* __restrict__ sent, const float* __restrict__ emb,
    const float* __restrict__ Wf, const float* __restrict__ bfv,
    const float* __restrict__ Wb, const float* __restrict__ bbv)
{
    extern __shared__ float Xs[];       // [64][256]
    __shared__ int tok[B_];
    int l   = blockIdx.x;
    int tid = threadIdx.x;
    if (tid < B_) tok[tid] = sent[tid*L_ + l];
    __syncthreads();
    float4* Xs4 = (float4*)Xs;
    #pragma unroll
    for (int i = 0; i < 16; i++) {
        int e = i*256 + tid;
        int r = e >> 6, kq = e & 63;
        Xs4[e] = ((const float4*)emb)[(size_t)tok[r]*64 + kq];
    }
    __syncthreads();

    int j   = blockIdx.y*256 + tid;
    int dir = j >> 10, jj = j & 1023;
    const float* W = dir ? Wb : Wf;
    const ulonglong2* W2 = (const ulonglong2*)(W + (size_t)jj*256);
    const ulonglong2* X2 = (const ulonglong2*)Xs;

    u64 acc2[64];
    #pragma unroll
    for (int r = 0; r < 64; r++) acc2[r] = 0ull;

    #pragma unroll 1
    for (int k4 = 0; k4 < 64; k4++) {
        ulonglong2 w = W2[k4];
        #pragma unroll
        for (int r = 0; r < 64; r++) {
            ulonglong2 x = X2[r*64 + k4];
            acc2[r] = fma2(w.x, x.x, acc2[r]);
            acc2[r] = fma2(w.y, x.y, acc2[r]);
        }
    }
    float bias = (dir ? bbv : bfv)[jj];
    float* outp = g_gx + (((size_t)dir*L_ + l)*B_)*1024 + jj;
    #pragma unroll
    for (int r = 0; r < 64; r++) {
        float2 p = unpack2(acc2[r]);
        outp[(size_t)r*1024] = p.x + p.y + bias;
    }
}

// ---------------- persistent bidirectional LSTM recurrence ----------------
// 128 CTAs: cid>>6 = dir, cid&63 = 4-hidden-unit slice. 256 threads =
// (khalf 2) x (batch-pair 32) x (jl 4): thread computes 2 batch x 4 gates over K/2.
// Sync: per-producer monotonic counters, release-store / acquire-load (no atomics,
// no shared hot line).
__global__ __launch_bounds__(256) void k_lstm(const float* __restrict__ Whf,
                                              const float* __restrict__ Whb)
{
    extern __shared__ float sm[];
    float* Hs = sm;                    // [64][260]
    float* Ws = sm + 64*260;           // [16][260]
    float* Ps = sm + 64*260 + 16*260;  // [8][128] partial sums (kh=1 half)
    int cid = blockIdx.x;
    int d   = cid >> 6;
    int pid = cid & 63;                // producer id within direction
    int hb  = pid * 4;
    int tid = threadIdx.x;
    int kh  = tid >> 7;                // K half
    int bp  = (tid >> 2) & 31;         // batch pair: b0=bp, b1=bp+32
    int jl  = tid & 3;                 // local hidden unit
    int b0 = bp, b1 = bp + 32;
    int hid = hb + jl;
    const float* W = d ? Whb : Whf;

    for (int i = 0; i < 16; i++) {
        int e = i*256 + tid;
        int rl = e >> 8, k = e & 255;
        int g = rl >> 2, j2 = rl & 3;
        Ws[rl*260 + k] = W[((size_t)(g*H_ + hb + j2))*H_ + k];
    }

    float c0 = 0.f, c1 = 0.f;
    int*       my_cnt  = g_cnt + d*64 + pid;
    const int* poll_p  = g_cnt + d*64 + (tid & 63);

    for (int s = 0; s < L_; s++) {
        int t = d ? (L_-1-s) : s;
        // input-gate loads (independent of h) — issue before the wait
        float a00, a01, a02, a03, a10, a11, a12, a13;
        if (kh == 0) {
            const float* gx0 = g_gx + (((size_t)d*L_ + t)*B_ + b0)*1024 + hid;
            const float* gx1 = g_gx + (((size_t)d*L_ + t)*B_ + b1)*1024 + hid;
            a00 = gx0[0]; a01 = gx0[256]; a02 = gx0[512]; a03 = gx0[768];
            a10 = gx1[0]; a11 = gx1[256]; a12 = gx1[512]; a13 = gx1[768];
        }

        if (s == 0) {
            #pragma unroll
            for (int i = 0; i < 16; i++) {
                int e = i*256 + tid; int r = e >> 6, kq = e & 63;
                ((float4*)(Hs + r*260))[kq] = make_float4(0.f,0.f,0.f,0.f);
            }
        } else {
            int tprev = d ? (t+1) : (t-1);
            if (tid < 64) {
                while (ld_acquire(poll_p) < s) { }
            }
            __syncthreads();
            const float4* src = (const float4*)(g_h + (((size_t)d*L_ + tprev)*B_)*H_);
            #pragma unroll
            for (int i = 0; i < 16; i++) {
                int e = i*256 + tid; int r = e >> 6, kq = e & 63;
                ((float4*)(Hs + r*260))[kq] = src[e];
            }
        }
        __syncthreads();

        const ulonglong2* h0p = (const ulonglong2*)(Hs + b0*260 + kh*128);
        const ulonglong2* h1p = (const ulonglong2*)(Hs + b1*260 + kh*128);
        const ulonglong2* w0p = (const ulonglong2*)(Ws + ( 0+jl)*260 + kh*128);
        const ulonglong2* w1p = (const ulonglong2*)(Ws + ( 4+jl)*260 + kh*128);
        const ulonglong2* w2p = (const ulonglong2*)(Ws + ( 8+jl)*260 + kh*128);
        const ulonglong2* w3p = (const ulonglong2*)(Ws + (12+jl)*260 + kh*128);
        u64 A00=0ull,A01=0ull,A02=0ull,A03=0ull;
        u64 A10=0ull,A11=0ull,A12=0ull,A13=0ull;
        #pragma unroll 8
        for (int k4 = 0; k4 < 32; k4++) {
            ulonglong2 x0 = h0p[k4];
            ulonglong2 x1 = h1p[k4];
            ulonglong2 w0 = w0p[k4], w1 = w1p[k4], w2 = w2p[k4], w3 = w3p[k4];
            A00 = fma2(w0.x, x0.x, A00); A00 = fma2(w0.y, x0.y, A00);
            A01 = fma2(w1.x, x0.x, A01); A01 = fma2(w1.y, x0.y, A01);
            A02 = fma2(w2.x, x0.x, A02); A02 = fma2(w2.y, x0.y, A02);
            A03 = fma2(w3.x, x0.x, A03); A03 = fma2(w3.y, x0.y, A03);
            A10 = fma2(w0.x, x1.x, A10); A10 = fma2(w0.y, x1.y, A10);
            A11 = fma2(w1.x, x1.x, A11); A11 = fma2(w1.y, x1.y, A11);
            A12 = fma2(w2.x, x1.x, A12); A12 = fma2(w2.y, x1.y, A12);
            A13 = fma2(w3.x, x1.x, A13); A13 = fma2(w3.y, x1.y, A13);
        }
        float2 p00=unpack2(A00), p01=unpack2(A01), p02=unpack2(A02), p03=unpack2(A03);
        float2 p10=unpack2(A10), p11=unpack2(A11), p12=unpack2(A12), p13=unpack2(A13);
        float s00=p00.x+p00.y, s01=p01.x+p01.y, s02=p02.x+p02.y, s03=p03.x+p03.y;
        float s10=p10.x+p10.y, s11=p11.x+p11.y, s12=p12.x+p12.y, s13=p13.x+p13.y;

        if (kh == 1) {
            int c = tid - 128;          // 0..127
            Ps[0*128 + c] = s00; Ps[1*128 + c] = s01;
            Ps[2*128 + c] = s02; Ps[3*128 + c] = s03;
            Ps[4*128 + c] = s10; Ps[5*128 + c] = s11;
            Ps[6*128 + c] = s12; Ps[7*128 + c] = s13;
        }
        __syncthreads();
        if (kh == 0) {
            a00 += s00 + Ps[0*128 + tid]; a01 += s01 + Ps[1*128 + tid];
            a02 += s02 + Ps[2*128 + tid]; a03 += s03 + Ps[3*128 + tid];
            a10 += s10 + Ps[4*128 + tid]; a11 += s11 + Ps[5*128 + tid];
            a12 += s12 + Ps[6*128 + tid]; a13 += s13 + Ps[7*128 + tid];

            float ig0 = fsig(a00), fg0 = fsig(a01), gg0 = ftanh(a02), og0 = fsig(a03);
            c0 = fg0*c0 + ig0*gg0;
            float h0 = og0 * ftanh(c0);
            float ig1 = fsig(a10), fg1 = fsig(a11), gg1 = ftanh(a12), og1 = fsig(a13);
            c1 = fg1*c1 + ig1*gg1;
            float h1 = og1 * ftanh(c1);
            g_h[(((size_t)d*L_ + t)*B_ + b0)*H_ + hid] = h0;
            g_h[(((size_t)d*L_ + t)*B_ + b1)*H_ + hid] = h1;
        }
        __syncthreads();
        if (tid == 0) st_release(my_cnt, s + 1);
    }
}

// ---------------- emission GEMM ----------------
__global__ __launch_bounds__(768) void k_emit(const float* __restrict__ Wem,
                                              const float* __restrict__ bem)
{
    extern __shared__ float smc[];
    float* Hcat = smc;            // [64][520]
    float* Wsm  = smc + 64*520;   // [12][516]
    int l   = blockIdx.x;
    int tid = threadIdx.x;
    const float4* hf  = (const float4*)(g_h + ((size_t)0*L_ + l)*B_*H_);
    const float4* hbk = (const float4*)(g_h + ((size_t)1*L_ + l)*B_*H_);
    for (int e = tid; e < 4096; e += 768) {
        int r = e >> 6, kq = e & 63;
        ((float4*)(Hcat + r*520))[kq]       = hf[e];
        ((float4*)(Hcat + r*520 + 256))[kq] = hbk[e];
    }
    for (int e = tid; e < 12*512; e += 768)
        Wsm[(e >> 9)*516 + (e & 511)] = Wem[e];
    __syncthreads();

    int b = tid / 12, tg = tid - b*12;
    float acc = bem[tg];
    const float4* hrow = (const float4*)(Hcat + b*520);
    const float4* wrow = (const float4*)(Wsm + tg*516);
    #pragma unroll 8
    for (int k4 = 0; k4 < 128; k4++) {
        float4 x = hrow[k4]; float4 w = wrow[k4];
        acc += w.x*x.x + w.y*x.y + w.z*x.z + w.w*x.w;
    }
    g_emit[((size_t)l*B_ + b)*T_ + tg] = acc;
}

// ---------------- CRF NLL per batch element: one warp per b ----------------
__global__ void k_crf(const int* __restrict__ tags, const float* __restrict__ trans)
{
    int b = blockIdx.x;
    int lane = threadIdx.x;
    __shared__ float tr[T_*T_];
    for (int i = lane; i < T_*T_; i += 32) tr[i] = trans[i];
    __syncwarp();
    const unsigned FULL = 0xffffffffu;
    int mylane = (lane < T_) ? lane : 0;
    float alpha = (lane < T_) ? g_emit[(size_t)b*T_ + lane] : 0.f;
    for (int l = 1; l < L_; l++) {
        float v[T_];
        float m = -1e30f;
        #pragma unroll
        for (int t2 = 0; t2 < T_; t2++) {
            float at = __shfl_sync(FULL, alpha, t2);
            float vv = at + tr[t2*T_ + mylane];
            v[t2] = vv;
            m = fmaxf(m, vv);
        }
        float ssum = 0.f;
        #pragma unroll
        for (int t2 = 0; t2 < T_; t2++) ssum += __expf(v[t2] - m);
        float e = (lane < T_) ? g_emit[((size_t)l*B_ + b)*T_ + lane] : 0.f;
        alpha = m + __logf(ssum) + e;
    }
    float am = (lane < T_) ? alpha : -1e30f;
    float mm = am;
    for (int o = 16; o; o >>= 1) mm = fmaxf(mm, __shfl_xor_sync(FULL, mm, o));
    float es = (lane < T_) ? __expf(alpha - mm) : 0.f;
    for (int o = 16; o; o >>= 1) es += __shfl_xor_sync(FULL, es, o);
    float logZ = mm + __logf(es);

    float eg = 0.f, tg2 = 0.f;
    for (int l = lane; l < L_; l += 32) {
        int tv = tags[b*L_ + l];
        eg += g_emit[((size_t)l*B_ + b)*T_ + tv];
    }
    for (int l = lane; l < L_-1; l += 32) {
        int t0v = tags[b*L_ + l], t1v = tags[b*L_ + l + 1];
        tg2 += tr[t0v*T_ + t1v];
    }
    for (int o = 16; o; o >>= 1) {
        eg  += __shfl_xor_sync(FULL, eg,  o);
        tg2 += __shfl_xor_sync(FULL, tg2, o);
    }
    if (lane == 0) g_nll[b] = logZ - eg - tg2;
}

__global__ void k_mean(float* out)
{
    if (threadIdx.x == 0) {
        float s = 0.f;
        for (int i = 0; i < B_; i++) s += g_nll[i];
        out[0] = s / (float)B_;
    }
}

// ---------------- launch ----------------
extern "C" void kernel_launch(void* const* d_in, const int* in_sizes, int n_in,
                              void* d_out, int out_size)
{
    const int*   sent  = (const int*)  d_in[0];
    const int*   tags  = (const int*)  d_in[1];
    const float* emb   = (const float*)d_in[2];
    const float* Wihf  = (const float*)d_in[3];
    const float* Whhf  = (const float*)d_in[4];
    const float* bf    = (const float*)d_in[5];
    const float* Wihb  = (const float*)d_in[6];
    const float* Whhb  = (const float*)d_in[7];
    const float* bb    = (const float*)d_in[8];
    const float* Wem   = (const float*)d_in[9];
    const float* bem   = (const float*)d_in[10];
    const float* trans = (const float*)d_in[11];
    float* out = (float*)d_out;

    const int lstm_smem = (64*260 + 16*260 + 8*128)*4;
    cudaFuncSetAttribute(k_ingate, cudaFuncAttributeMaxDynamicSharedMemorySize, 64*256*4);
    cudaFuncSetAttribute(k_lstm,   cudaFuncAttributeMaxDynamicSharedMemorySize, lstm_smem);
    cudaFuncSetAttribute(k_emit,   cudaFuncAttributeMaxDynamicSharedMemorySize, (64*520 + 12*516)*4);

    k_reset<<<1, 128>>>();
    dim3 gA(L_, 8);
    k_ingate<<<gA, 256, 64*256*4>>>(sent, emb, Wihf, bf, Wihb, bb);
    k_lstm<<<128, 256, lstm_smem>>>(Whhf, Whhb);
    k_emit<<<L_, 768, (64*520 + 12*516)*4>>>(Wem, bem);
    k_crf<<<B_, 32>>>(tags, trans);
    k_mean<<<1, 32>>>(out);
}